// round 4
// baseline (speedup 1.0000x reference)
#include <cuda_runtime.h>
#include <math.h>
#include <math_constants.h>

#define BATCH 64
#define DIM   768
#define HW    3136          // 56*56
#define FREQ  256
#define NE    16
#define TOPK  4
#define NBLOCKS ((BATCH * DIM) / 8)   // 6144 blocks of 256 threads (8 warps)

// scratch (device globals: zero-initialized; tail block restores zeros each run)
__device__ float g_logits_main[BATCH * NE];   // atomic-accumulated pooled @ gate_w.T
__device__ float g_logits_freq[BATCH * NE];   // freq_emb @ freq_gate_w.T (plain writes)
__device__ unsigned int g_counter;            // last-block-done counter

// ---------------------------------------------------------------------------
// Fused kernel: pooled mean + gating GEMM (atomics) + last-block epilogue.
// __launch_bounds__(256, 8) caps regs at 32 so the hot streaming phase keeps
// 8 blocks/SM (any epilogue spill cost is paid by ONE block out of 6144).
// Output (float32): gates[64*16] | top_k_indices[64*4] | top_k_values[64*4] | aux_loss
// ---------------------------------------------------------------------------
__global__ void __launch_bounds__(256, 8) routing_fused_kernel(
    const float* __restrict__ x,
    const float* __restrict__ gate_w,
    const float* __restrict__ freq_emb,
    const float* __restrict__ fgate_w,
    const float* __restrict__ noise,
    const float* __restrict__ complexity,
    float* __restrict__ out) {

    const int tid = threadIdx.x;
    const int warp_id = (blockIdx.x * blockDim.x + tid) >> 5;
    const int lane = tid & 31;
    const int b = warp_id / DIM;
    const int d = warp_id - b * DIM;

    // ---- phase 1: stream one (b,d) row of x, reduce, scatter to logits ----
    const float4* row = reinterpret_cast<const float4*>(x + (size_t)warp_id * HW);
    float s = 0.0f;
#pragma unroll
    for (int t = 0; t < 3; ++t) {           // 784 float4: 3 x (8 x 32 lanes) + 16
        float4 v[8];
#pragma unroll
        for (int k = 0; k < 8; ++k)
            v[k] = __ldcs(&row[lane + 32 * (t * 8 + k)]);
#pragma unroll
        for (int k = 0; k < 8; ++k)
            s += (v[k].x + v[k].y) + (v[k].z + v[k].w);
    }
    if (lane < 16) {
        float4 v = __ldcs(&row[768 + lane]);
        s += (v.x + v.y) + (v.z + v.w);
    }
#pragma unroll
    for (int m = 16; m; m >>= 1) s += __shfl_xor_sync(0xffffffffu, s, m);

    const float pooled = s * (1.0f / (float)HW);
    if (lane < NE)
        atomicAdd(&g_logits_main[b * NE + lane], pooled * gate_w[lane * DIM + d]);

    if (d < NE) {                            // freq-emb logits ride along
        const int e = d;
        const float4* fr  = reinterpret_cast<const float4*>(freq_emb + b * FREQ);
        const float4* fgr = reinterpret_cast<const float4*>(fgate_w  + e * FREQ);
        float f = 0.0f;
#pragma unroll
        for (int j = 0; j < 2; ++j) {        // 64 float4 / 32 lanes
            float4 a = fr[lane + 32 * j];
            float4 w = fgr[lane + 32 * j];
            f += a.x * w.x + a.y * w.y + a.z * w.z + a.w * w.w;
        }
#pragma unroll
        for (int m = 16; m; m >>= 1) f += __shfl_xor_sync(0xffffffffu, f, m);
        if (lane == 0) g_logits_freq[b * NE + e] = f;
    }

    // ---- last-block election ----
    __shared__ unsigned int s_last;
    __threadfence();                         // make logits visible before ticket
    if (tid == 0) {
        unsigned int v = atomicAdd(&g_counter, 1u);
        s_last = (v == (unsigned int)(NBLOCKS - 1)) ? 1u : 0u;
    }
    __syncthreads();
    if (!s_last) return;

    // ---- phase 2 (tail block only): softmax / top-k / gates / aux loss ----
    __shared__ float s_clean[BATCH * NE];
    __shared__ float s_p[BATCH * NE];

    const int e    = tid & 15;
    const int half = lane & 16;              // base lane of my 16-lane group
    const float noise_std = 1.0f / (float)NE;

#pragma unroll 1
    for (int iter = 0; iter < 4; ++iter) {   // 256 threads x 4 = 1024 (b,e)
        const int bb = iter * 16 + (tid >> 4);
        const int idx = bb * NE + e;
        const float logit = g_logits_main[idx] + g_logits_freq[idx];
        const float noisy = logit + noise[idx] * noise_std;

        // clean softmax over the 16-lane row group
        float cm = logit;
#pragma unroll
        for (int m = 8; m; m >>= 1) cm = fmaxf(cm, __shfl_xor_sync(0xffffffffu, cm, m));
        float ce = expf(logit - cm);
        float cs = ce;
#pragma unroll
        for (int m = 8; m; m >>= 1) cs += __shfl_xor_sync(0xffffffffu, cs, m);
        const float clean = ce / cs;

        // noisy softmax
        float nm = noisy;
#pragma unroll
        for (int m = 8; m; m >>= 1) nm = fmaxf(nm, __shfl_xor_sync(0xffffffffu, nm, m));
        float ne_ = expf(noisy - nm);
        float ns = ne_;
#pragma unroll
        for (int m = 8; m; m >>= 1) ns += __shfl_xor_sync(0xffffffffu, ns, m);
        const float score = ne_ / ns;

        // rank of my noisy logit within the row (ties: lower index wins)
        int rank = 0;
#pragma unroll
        for (int j = 0; j < 16; ++j) {
            float vj = __shfl_sync(0xffffffffu, noisy, half + j);
            rank += (vj > noisy) || (vj == noisy && j < e);
        }

        // threshold = k-th largest noisy logit
        float thr = (rank == TOPK - 1) ? noisy : -CUDART_INF_F;
#pragma unroll
        for (int m = 8; m; m >>= 1) thr = fmaxf(thr, __shfl_xor_sync(0xffffffffu, thr, m));

        out[idx] = (rank < TOPK) ? score : 0.0f;
        if (rank < TOPK) {
            out[BATCH * NE + bb * TOPK + rank]                = (float)e;  // indices
            out[BATCH * NE + BATCH * TOPK + bb * TOPK + rank] = score;     // values
        }

        // p = 1 - norm_cdf((thr - logit)/noise_std)
        s_p[idx]     = 0.5f * erfcf((thr - logit) * (float)NE * 0.70710678118654752f);
        s_clean[idx] = clean;
    }
    __syncthreads();

    // aux loss: deterministic reduction by warp 0
    if (tid < 32) {
        float imp = 0.0f, pm = 0.0f;
        if (tid < 16) {
            for (int bb = 0; bb < BATCH; ++bb) {
                imp += s_clean[bb * NE + tid];
                pm  += s_p[bb * NE + tid];
            }
            imp *= complexity[tid];
            pm  *= (1.0f / (float)BATCH);
        }
        float im = imp, pmn = pm;
#pragma unroll
        for (int m = 8; m; m >>= 1) {
            im  += __shfl_xor_sync(0xffffffffu, im,  m);
            pmn += __shfl_xor_sync(0xffffffffu, pmn, m);
        }
        im  *= (1.0f / (float)NE);
        pmn *= (1.0f / (float)NE);
        float dv = (tid < 16) ? (imp - im)  * (imp - im)  : 0.0f;
        float dp = (tid < 16) ? (pm  - pmn) * (pm  - pmn) : 0.0f;
#pragma unroll
        for (int m = 8; m; m >>= 1) {
            dv += __shfl_xor_sync(0xffffffffu, dv, m);
            dp += __shfl_xor_sync(0xffffffffu, dp, m);
        }
        if (tid == 0) {
            float imp_loss  = (dv / (float)(NE - 1)) / ((im  + 1e-8f) * (im  + 1e-8f));
            float load_loss = (dp / (float)(NE - 1)) / ((pmn + 1e-8f) * (pmn + 1e-8f));
            out[BATCH * NE + 2 * BATCH * TOPK] = 0.5f * imp_loss + 0.5f * load_loss;
        }
    }
    __syncthreads();

    // restore scratch state for the next graph replay (deterministic)
#pragma unroll
    for (int iter = 0; iter < 4; ++iter)
        g_logits_main[iter * 256 + tid] = 0.0f;
    if (tid == 0) g_counter = 0u;
}

// ---------------------------------------------------------------------------
extern "C" void kernel_launch(void* const* d_in, const int* in_sizes, int n_in,
                              void* d_out, int out_size) {
    const float* x          = (const float*)d_in[0];
    const float* freq_emb   = (const float*)d_in[1];
    const float* gate_w     = (const float*)d_in[2];
    const float* fgate_w    = (const float*)d_in[3];
    const float* complexity = (const float*)d_in[4];
    const float* noise      = (const float*)d_in[5];
    float* out = (float*)d_out;

    routing_fused_kernel<<<NBLOCKS, 256>>>(x, gate_w, freq_emb, fgate_w,
                                           noise, complexity, out);
}

// round 5
// speedup vs baseline: 1.0630x; 1.0630x over previous
#include <cuda_runtime.h>
#include <math.h>
#include <math_constants.h>

#define BATCH 64
#define DIM   768
#define HW    3136          // 56*56
#define FREQ  256
#define NE    16
#define TOPK  4

// scratch (device globals: zero-initialized; finish kernel restores zeros)
__device__ float g_logits_main[BATCH * NE];   // atomic-accumulated pooled @ gate_w.T
__device__ float g_logits_freq[BATCH * NE];   // freq_emb @ freq_gate_w.T (plain writes)

// ---------------------------------------------------------------------------
// Kernel A (primary): pooled mean over HW + gating GEMM via per-warp atomics.
// One warp per (b,d) row of x. This is the R2 streaming kernel (31 regs,
// ~87% DRAM). NO gpu-scope fences, NO tail election — those throttled the
// stream by ~14us in R3/R4 (CCTL.IVALL per block).
// ---------------------------------------------------------------------------
__global__ void __launch_bounds__(256) pool_gate_kernel(
    const float* __restrict__ x,
    const float* __restrict__ gate_w,
    const float* __restrict__ freq_emb,
    const float* __restrict__ fgate_w) {

    const int warp_id = (blockIdx.x * blockDim.x + threadIdx.x) >> 5;
    const int lane = threadIdx.x & 31;
    const int b = warp_id / DIM;
    const int d = warp_id - b * DIM;

    const float4* row = reinterpret_cast<const float4*>(x + (size_t)warp_id * HW);
    float s = 0.0f;
#pragma unroll
    for (int t = 0; t < 3; ++t) {           // 784 float4: 3 x (8 x 32 lanes) + 16
        float4 v[8];
#pragma unroll
        for (int k = 0; k < 8; ++k)
            v[k] = __ldcs(&row[lane + 32 * (t * 8 + k)]);
#pragma unroll
        for (int k = 0; k < 8; ++k)
            s += (v[k].x + v[k].y) + (v[k].z + v[k].w);
    }
    if (lane < 16) {
        float4 v = __ldcs(&row[768 + lane]);
        s += (v.x + v.y) + (v.z + v.w);
    }
#pragma unroll
    for (int m = 16; m; m >>= 1) s += __shfl_xor_sync(0xffffffffu, s, m);

    const float pooled = s * (1.0f / (float)HW);
    if (lane < NE)
        atomicAdd(&g_logits_main[b * NE + lane], pooled * gate_w[lane * DIM + d]);

    if (d < NE) {                            // freq-emb logits ride along
        const int e = d;
        const float4* fr  = reinterpret_cast<const float4*>(freq_emb + b * FREQ);
        const float4* fgr = reinterpret_cast<const float4*>(fgate_w  + e * FREQ);
        float f = 0.0f;
#pragma unroll
        for (int j = 0; j < 2; ++j) {        // 64 float4 / 32 lanes
            float4 a = fr[lane + 32 * j];
            float4 w = fgr[lane + 32 * j];
            f += a.x * w.x + a.y * w.y + a.z * w.z + a.w * w.w;
        }
#pragma unroll
        for (int m = 16; m; m >>= 1) f += __shfl_xor_sync(0xffffffffu, f, m);
        if (lane == 0) g_logits_freq[b * NE + e] = f;
    }
}

// ---------------------------------------------------------------------------
// Kernel B (PDL secondary): softmax / top-k / gates / aux loss.
// Launched with programmatic stream serialization: it starts while the pool
// grid is draining, runs its input-independent prelude (noise loads), then
// cudaGridDependencySynchronize() waits for pool completion + visibility.
// Re-zeros g_logits_main for the next graph replay (same-thread read->write).
// Output (float32): gates[64*16] | top_k_indices[64*4] | top_k_values[64*4] | aux_loss
// ---------------------------------------------------------------------------
__global__ void finish_kernel(const float* __restrict__ noise,
                              const float* __restrict__ complexity,
                              float* __restrict__ out) {
    __shared__ float s_clean[BATCH * NE];
    __shared__ float s_p[BATCH * NE];

    const int tid  = threadIdx.x;          // 0..1023
    const int b    = tid >> 4;
    const int e    = tid & 15;
    const int lane = tid & 31;
    const int half = lane & 16;            // base lane of my 16-lane group

    // ---- prelude: everything that does NOT depend on the primary ----
    const float noise_std = 1.0f / (float)NE;
    const float my_noise  = noise[tid] * noise_std;      // global load, hidden under pool
    const float my_cplx   = (tid < NE) ? complexity[tid] : 0.0f;

    // ---- wait for pool_gate grid completion (full memory visibility) ----
    cudaGridDependencySynchronize();

    const float logit = g_logits_main[tid] + g_logits_freq[tid];
    g_logits_main[tid] = 0.0f;             // restore for next replay (own element)
    const float noisy = logit + my_noise;

    // clean softmax over the 16-lane row group
    float cm = logit;
#pragma unroll
    for (int m = 8; m; m >>= 1) cm = fmaxf(cm, __shfl_xor_sync(0xffffffffu, cm, m));
    float ce = expf(logit - cm);
    float cs = ce;
#pragma unroll
    for (int m = 8; m; m >>= 1) cs += __shfl_xor_sync(0xffffffffu, cs, m);
    const float clean = ce / cs;

    // noisy softmax
    float nm = noisy;
#pragma unroll
    for (int m = 8; m; m >>= 1) nm = fmaxf(nm, __shfl_xor_sync(0xffffffffu, nm, m));
    float ne_ = expf(noisy - nm);
    float ns = ne_;
#pragma unroll
    for (int m = 8; m; m >>= 1) ns += __shfl_xor_sync(0xffffffffu, ns, m);
    const float score = ne_ / ns;

    // rank of my noisy logit within the row (ties: lower index wins, jax top_k)
    int rank = 0;
#pragma unroll
    for (int j = 0; j < 16; ++j) {
        float vj = __shfl_sync(0xffffffffu, noisy, half + j);
        rank += (vj > noisy) || (vj == noisy && j < e);
    }

    // threshold = k-th largest noisy logit (rank == TOPK-1)
    float thr = (rank == TOPK - 1) ? noisy : -CUDART_INF_F;
#pragma unroll
    for (int m = 8; m; m >>= 1) thr = fmaxf(thr, __shfl_xor_sync(0xffffffffu, thr, m));

    // outputs: gates / indices / values
    out[tid] = (rank < TOPK) ? score : 0.0f;
    if (rank < TOPK) {
        out[BATCH * NE + b * TOPK + rank]                 = (float)e;  // indices
        out[BATCH * NE + BATCH * TOPK + b * TOPK + rank]  = score;     // values
    }

    // p = 1 - norm_cdf((thr - logit)/noise_std) = 0.5*erfc(arg/sqrt(2))
    const float p = 0.5f * erfcf((thr - logit) * (float)NE * 0.70710678118654752f);

    s_clean[tid] = clean;
    s_p[tid]     = p;
    __syncthreads();

    // aux loss: deterministic reduction by warp 0
    if (tid < 32) {
        float imp = 0.0f, pm = 0.0f;
        if (tid < 16) {
            for (int bb = 0; bb < BATCH; ++bb) {
                imp += s_clean[bb * NE + tid];
                pm  += s_p[bb * NE + tid];
            }
            imp *= my_cplx;
            pm  *= (1.0f / (float)BATCH);
        }
        float im = imp, pmn = pm;
#pragma unroll
        for (int m = 8; m; m >>= 1) {
            im  += __shfl_xor_sync(0xffffffffu, im,  m);
            pmn += __shfl_xor_sync(0xffffffffu, pmn, m);
        }
        im  *= (1.0f / (float)NE);
        pmn *= (1.0f / (float)NE);
        float dv = (tid < 16) ? (imp - im)  * (imp - im)  : 0.0f;
        float dp = (tid < 16) ? (pm  - pmn) * (pm  - pmn) : 0.0f;
#pragma unroll
        for (int m = 8; m; m >>= 1) {
            dv += __shfl_xor_sync(0xffffffffu, dv, m);
            dp += __shfl_xor_sync(0xffffffffu, dp, m);
        }
        if (tid == 0) {
            float imp_loss  = (dv / (float)(NE - 1)) / ((im  + 1e-8f) * (im  + 1e-8f));
            float load_loss = (dp / (float)(NE - 1)) / ((pmn + 1e-8f) * (pmn + 1e-8f));
            out[BATCH * NE + 2 * BATCH * TOPK] = 0.5f * imp_loss + 0.5f * load_loss;
        }
    }
}

// ---------------------------------------------------------------------------
extern "C" void kernel_launch(void* const* d_in, const int* in_sizes, int n_in,
                              void* d_out, int out_size) {
    const float* x          = (const float*)d_in[0];
    const float* freq_emb   = (const float*)d_in[1];
    const float* gate_w     = (const float*)d_in[2];
    const float* fgate_w    = (const float*)d_in[3];
    const float* complexity = (const float*)d_in[4];
    const float* noise      = (const float*)d_in[5];
    float* out = (float*)d_out;

    // A: streaming pool + gating GEMM — 6144 blocks, 8 warps each
    pool_gate_kernel<<<(BATCH * DIM) / 8, 256>>>(x, gate_w, freq_emb, fgate_w);

    // B: epilogue with programmatic dependent launch (overlaps launch+prelude)
    cudaLaunchAttribute attrs[1];
    attrs[0].id = cudaLaunchAttributeProgrammaticStreamSerialization;
    attrs[0].val.programmaticStreamSerializationAllowed = 1;

    cudaLaunchConfig_t cfg = {};
    cfg.gridDim  = dim3(1, 1, 1);
    cfg.blockDim = dim3(BATCH * NE, 1, 1);
    cfg.dynamicSmemBytes = 0;
    cfg.stream = 0;
    cfg.attrs = attrs;
    cfg.numAttrs = 1;

    cudaLaunchKernelEx(&cfg, finish_kernel, noise, complexity, out);
}